// round 11
// baseline (speedup 1.0000x reference)
#include <cuda_runtime.h>
#include <cuda.h>
#include <cuda_fp16.h>
#include <math.h>
#include <stdint.h>

#define SP 65536        /* 16^4 */
#define CIN 32
#define H 128
#define COUT 32
#define SED 8

// ---------------- scratch (device globals) ----------------
__device__ float g_h1[H * SP];                       // conv1 out (fp32, [c][v])
__device__ __align__(1024) __half g_h1h[SP * H];     // gelu1 out, channel-last fp16 [v][c]
__device__ __align__(1024) __half g_w2h[81 * H * H]; // conv2 weights fp16 [tap][o][c]
__device__ float g_h2[H * SP];                       // conv2 out [o][v] -> gelu'd in place
__device__ float g_pre[COUT * SP];
__device__ float g_part0[512 * 2];                   // stats partials: x
__device__ float g_part1[512 * 2];                   // h1
__device__ float g_part2[512 * 2];                   // h2
__device__ float g_part3[512 * 2];                   // pre
__device__ float g_chsump[8192];                     // SE per-block partial sums
__device__ unsigned g_cnt[8];                        // done-counters (self-resetting)
__device__ float g_w1eff[H * CIN];
__device__ float g_bias1[H];
__device__ float g_a1[H], g_b1[H], g_a2[H], g_b2[H], g_a3[COUT], g_b3[COUT];
__device__ float g_w3eff[COUT * H];

// ---------------- PTX helpers (plain sm_90/sm_80 features only) ----------------
__device__ __forceinline__ uint32_t smem_u32(const void* p) {
    uint32_t a;
    asm("{ .reg .u64 t; cvta.to.shared.u64 t, %1; cvt.u32.u64 %0, t; }" : "=r"(a) : "l"(p));
    return a;
}

#define MBARRIER_INIT(mbar, cnt) \
    asm volatile("mbarrier.init.shared.b64 [%0], %1;" :: "r"((uint32_t)(mbar)), "r"((uint32_t)(cnt)) : "memory")

#define MBARRIER_EXPECT_TX(mbar, bytes) \
    asm volatile("mbarrier.arrive.expect_tx.shared.b64 _, [%0], %1;" :: "r"((uint32_t)(mbar)), "r"((uint32_t)(bytes)) : "memory")

#define MBARRIER_ARRIVE(mbar) \
    asm volatile("mbarrier.arrive.shared.b64 _, [%0];" :: "r"((uint32_t)(mbar)) : "memory")

#define MBARRIER_WAIT_PARITY(mbar, ph) do { \
    uint32_t _m = (uint32_t)(mbar); uint32_t _p = (uint32_t)(ph); uint32_t _d; \
    asm volatile("{\n\t.reg .pred p;\n\t" \
        "mbarrier.try_wait.parity.acquire.cta.shared::cta.b64 p, [%1], %2;\n\t" \
        "selp.b32 %0, 1, 0, p;\n\t}" : "=r"(_d) : "r"(_m), "r"(_p) : "memory"); \
    if (!_d) { \
        asm volatile("{\n\t.reg .pred P1;\n\t" \
            "WL_%=:\n\t" \
            "mbarrier.try_wait.parity.acquire.cta.shared::cta.b64 P1, [%0], %1, 0x989680;\n\t" \
            "@P1 bra.uni WD_%=;\n\t" \
            "bra.uni WL_%=;\n\t" \
            "WD_%=:\n\t}" :: "r"(_m), "r"(_p) : "memory"); \
    } \
} while (0)

#define TMA_LOAD_3D(smem, map, c0, c1, c2, mbar) \
    asm volatile("cp.async.bulk.tensor.3d.shared::cta.global.tile.mbarrier::complete_tx::bytes " \
                 "[%0], [%1, {%2, %3, %4}], [%5];" \
                 :: "r"((uint32_t)(smem)), "l"(map), "r"((int)(c0)), "r"((int)(c1)), "r"((int)(c2)), \
                    "r"((uint32_t)(mbar)) : "memory")

#define TMA_LOAD_5D(smem, map, c0, c1, c2, c3, c4, mbar) \
    asm volatile("cp.async.bulk.tensor.5d.shared::cta.global.tile.mbarrier::complete_tx::bytes " \
                 "[%0], [%1, {%2, %3, %4, %5, %6}], [%7];" \
                 :: "r"((uint32_t)(smem)), "l"(map), "r"((int)(c0)), "r"((int)(c1)), "r"((int)(c2)), \
                    "r"((int)(c3)), "r"((int)(c4)), "r"((uint32_t)(mbar)) : "memory")

__device__ __forceinline__ void ldsm4(uint32_t* r, uint32_t addr) {
    asm volatile("ldmatrix.sync.aligned.m8n8.x4.shared.b16 {%0,%1,%2,%3}, [%4];"
                 : "=r"(r[0]), "=r"(r[1]), "=r"(r[2]), "=r"(r[3]) : "r"(addr));
}

__device__ __forceinline__ void mma16816(float* d, const uint32_t* a, const uint32_t* b) {
    asm volatile("mma.sync.aligned.m16n8k16.row.col.f32.f16.f16.f32 "
                 "{%0,%1,%2,%3}, {%4,%5,%6,%7}, {%8,%9}, {%0,%1,%2,%3};"
                 : "+f"(d[0]), "+f"(d[1]), "+f"(d[2]), "+f"(d[3])
                 : "r"(a[0]), "r"(a[1]), "r"(a[2]), "r"(a[3]), "r"(b[0]), "r"(b[1]));
}

__device__ __forceinline__ float geluf(float v) {
    return 0.5f * v * (1.0f + erff(v * 0.70710678118654752f));
}

// block-reduce (s,q); tid0 writes 2 floats to dst (partial record)
__device__ __forceinline__ void reduce2_part(float s, float q, float* dst) {
    __shared__ float rA[32], rB[32];
    const unsigned full = 0xffffffffu;
#pragma unroll
    for (int off = 16; off > 0; off >>= 1) {
        s += __shfl_down_sync(full, s, off);
        q += __shfl_down_sync(full, q, off);
    }
    int lane = threadIdx.x & 31, wid = threadIdx.x >> 5;
    int nw = (blockDim.x + 31) >> 5;
    if (lane == 0) { rA[wid] = s; rB[wid] = q; }
    __syncthreads();
    if (threadIdx.x == 0) {
        float S = 0.f, Q = 0.f;
        for (int w = 0; w < nw; w++) { S += rA[w]; Q += rB[w]; }
        dst[0] = S; dst[1] = Q;
    }
}

// last-block-done: true in the block that completes the counter; self-resets.
__device__ __forceinline__ bool last_block(int idx, unsigned n) {
    __shared__ unsigned lb_done;
    __threadfence();
    if (threadIdx.x == 0) {
        unsigned old = atomicAdd(&g_cnt[idx], 1u);
        lb_done = (old == n - 1) ? 1u : 0u;
        if (lb_done) g_cnt[idx] = 0;
    }
    __syncthreads();
    if (lb_done) __threadfence();
    return lb_done != 0;
}

// reduce n partial pairs cooperatively; broadcast mu, inv to whole block
__device__ __forceinline__ void finalize_stats(const float* part, int n, double invN,
                                               float& mu, float& inv) {
    __shared__ float rA[32], rB[32], bc2[2];
    float s = 0.f, q = 0.f;
    for (int i = threadIdx.x; i < n; i += blockDim.x) {
        s += part[2 * i];
        q += part[2 * i + 1];
    }
    const unsigned full = 0xffffffffu;
#pragma unroll
    for (int off = 16; off > 0; off >>= 1) {
        s += __shfl_down_sync(full, s, off);
        q += __shfl_down_sync(full, q, off);
    }
    int lane = threadIdx.x & 31, wid = threadIdx.x >> 5;
    int nw = (blockDim.x + 31) >> 5;
    if (lane == 0) { rA[wid] = s; rB[wid] = q; }
    __syncthreads();
    if (threadIdx.x == 0) {
        float S = 0.f, Q = 0.f;
        for (int w = 0; w < nw; w++) { S += rA[w]; Q += rB[w]; }
        bc2[0] = S; bc2[1] = Q;
    }
    __syncthreads();
    double m = (double)bc2[0] * invN;
    double var = (double)bc2[1] * invN - m * m;
    mu = (float)m;
    inv = (float)(1.0 / sqrt(var + 1e-5));
}

// ---------------- kernel 1: stats of x (blocks 0..511) + w2 transpose (512..1023) ----
__global__ void __launch_bounds__(256) k_stats0wt2(const float* __restrict__ x,
                                                   const float* __restrict__ w2,
                                                   const float* __restrict__ w1,
                                                   const float* __restrict__ g0w,
                                                   const float* __restrict__ g0b) {
    int bid = blockIdx.x;
    int tid = threadIdx.x;
    if (bid >= 512) {
        __shared__ float swt[2592];
        int base_oc = (bid - 512) * 32;
        const float* wsrc = w2 + base_oc * 81;
        for (int idx = tid; idx < 2592; idx += 256) swt[idx] = wsrc[idx];
        __syncthreads();
        for (int idx = tid; idx < 2592; idx += 256) {
            int t = idx >> 5;
            int ol = idx & 31;
            g_w2h[t * 16384 + base_oc + ol] = __float2half(swt[ol * 81 + t]);
        }
        return;
    }
    float s = 0.f, q = 0.f;
    int base = bid * 4096 + tid;
#pragma unroll
    for (int k = 0; k < 16; k++) {
        float v = x[base + k * 256];
        s += v;
        q = fmaf(v, v, q);
    }
    reduce2_part(s, q, &g_part0[bid * 2]);
    if (last_block(0, 512)) {
        float mu0, inv0;
        finalize_stats(g_part0, 512, 1.0 / (double)(CIN * SP), mu0, inv0);
        if (tid < 128) {
            int o = tid;
            float bias = 0.f;
            for (int c = 0; c < CIN; c++) {
                float a = inv0 * g0w[c];
                float b = g0b[c] - mu0 * a;
                float w = w1[o * CIN + c];
                g_w1eff[o * CIN + c] = w * a;
                bias = fmaf(w, b, bias);
            }
            g_bias1[o] = bias;
        }
    }
}

// ---------------- kernel 2: conv1 (1^4, 32->128); last block computes a1/b1 ---------
__global__ void __launch_bounds__(128) k_conv1(const float* __restrict__ x,
                                               const float* __restrict__ gn1w,
                                               const float* __restrict__ gn1b) {
    __shared__ __align__(16) float sw[H * CIN];
    __shared__ float sb[H];
    int tid = threadIdx.x;
    for (int i = tid; i < H * CIN; i += 128) sw[i] = g_w1eff[i];
    sb[tid] = g_bias1[tid];
    __syncthreads();
    int v = blockIdx.x * 128 + tid;
    float xr[CIN];
#pragma unroll
    for (int c = 0; c < CIN; c++) xr[c] = x[c * SP + v];
    float s = 0.f, q = 0.f;
    for (int o = 0; o < H; o++) {
        float acc = sb[o];
        const float4* wr = (const float4*)(&sw[o * CIN]);
#pragma unroll
        for (int c4 = 0; c4 < CIN / 4; c4++) {
            float4 w4 = wr[c4];
            acc = fmaf(w4.x, xr[4 * c4 + 0], acc);
            acc = fmaf(w4.y, xr[4 * c4 + 1], acc);
            acc = fmaf(w4.z, xr[4 * c4 + 2], acc);
            acc = fmaf(w4.w, xr[4 * c4 + 3], acc);
        }
        g_h1[o * SP + v] = acc;
        s += acc;
        q = fmaf(acc, acc, q);
    }
    reduce2_part(s, q, &g_part1[blockIdx.x * 2]);
    if (last_block(1, 512)) {
        float mu1, inv1;
        finalize_stats(g_part1, 512, 1.0 / (double)(H * SP), mu1, inv1);
        float a = gn1w[tid] * inv1;
        g_a1[tid] = a;
        g_b1[tid] = gn1b[tid] - mu1 * a;
    }
}

// ---------------- kernel 3: GN1 + GELU + transpose to channel-last fp16 -------------
__global__ void __launch_bounds__(256) k_gelu1t() {
    __shared__ __align__(16) __half sm[128 * 132];
    int v0 = blockIdx.x * 128;
    int tid = threadIdx.x;
    int cs = tid >> 7;
    int vs = tid & 127;
    for (int c = cs; c < 128; c += 2) {
        float val = g_h1[c * SP + v0 + vs];
        val = geluf(fmaf(g_a1[c], val, g_b1[c]));
        sm[vs * 132 + c] = __float2half(val);
    }
    __syncthreads();
    uint2* dst = (uint2*)&g_h1h[(size_t)v0 * 128];
    for (int idx = tid; idx < 4096; idx += 256) {
        int row = idx >> 5, part = idx & 31;
        const uint2* src = (const uint2*)&sm[row * 132 + part * 4];
        dst[idx] = *src;
    }
}

// ---------------- kernel 4: conv2, occupancy-2 variant ----------------
// CTA = 64 o x 256 voxels, 256 thr = 8 warps (2 o x 4 v). Grid 512 = (xy 256) x (o-half 2).
// 162 k-tiles (81 taps x 2 ch-halves of 64c). 2-stage pipeline, stage = A 8KB + B 32KB.
// 83KB smem/CTA -> 2 CTAs/SM: co-resident CTAs fill each other's barrier bubbles.
#define NSTAGE 2
#define STAGE_BYTES 40960
#define SM_DATA 1024
#define SMEM_TOTAL (SM_DATA + NSTAGE * STAGE_BYTES)   /* 82944 */
#define TILE_TX 40960

__device__ __forceinline__ void issue_tile(uint32_t sb, int i, int xx, int yy, int oh,
                                           const CUtensorMap* tw, const CUtensorMap* tx) {
    int s = i & 1;
    uint32_t fullb = sb + s * 8;
    MBARRIER_EXPECT_TX(fullb, TILE_TX);
    int ch = i & 1;
    int tap = i >> 1;
    int dx = tap / 27;
    int r27 = tap - dx * 27;
    int dy = r27 / 9;
    int r9 = r27 - dy * 9;
    int dz = r9 / 3;
    int dw = r9 - dz * 3;
    uint32_t D = sb + SM_DATA + s * STAGE_BYTES;
    TMA_LOAD_3D(D, tw, ch * 64, oh * 64, tap, fullb);
    TMA_LOAD_5D(D + 8192, tx, ch * 64, dw - 1, dz - 1, yy + dy - 1, xx + dx - 1, fullb);
}

__global__ void __launch_bounds__(256, 2) k_conv2mma(const __grid_constant__ CUtensorMap tw,
                                                     const __grid_constant__ CUtensorMap tx,
                                                     const float* __restrict__ gn2w,
                                                     const float* __restrict__ gn2b) {
    extern __shared__ __align__(1024) char smem[];
    uint32_t sb = smem_u32(smem);
    int tid = threadIdx.x;
    int lane = tid & 31, wid = tid >> 5;
    int wm = wid & 1, wn = wid >> 1;       // 2 o-tiles x 4 v-tiles
    int bx = blockIdx.x;
    int xy = bx >> 1, oh = bx & 1;
    int xx = xy >> 4, yy = xy & 15;

    if (tid == 0) {
        for (int s = 0; s < NSTAGE; s++) {
            MBARRIER_INIT(sb + s * 8, 1);                 // full: tx-based
            MBARRIER_INIT(sb + 32 + s * 8, 8);            // empty: 1 arrive/warp (lane 0)
        }
    }
    __syncthreads();
    if (tid == 0) {
        issue_tile(sb, 0, xx, yy, oh, &tw, &tx);
        issue_tile(sb, 1, xx, yy, oh, &tw, &tx);
    }

    float acc[2][8][4];
#pragma unroll
    for (int a = 0; a < 2; a++)
#pragma unroll
        for (int b = 0; b < 8; b++)
#pragma unroll
            for (int cc = 0; cc < 4; cc++) acc[a][b][cc] = 0.f;

    const uint32_t swx = (lane & 7) << 4;
    const uint32_t aSel = lane >> 4;
    const uint32_t bSel = (lane >> 3) & 1;
    const int aRow = wm * 32 + (lane & 15);
    const int bRow = wn * 64 + (lane & 7) + ((lane >> 4) << 3);

    for (int i = 0; i < 162; i++) {
        int st = i & 1;
        int ph = (i >> 1) & 1;
        MBARRIER_WAIT_PARITY(sb + st * 8, ph);
        uint32_t D = sb + SM_DATA + st * STAGE_BYTES;
        uint32_t aB0 = D + aRow * 128;
        uint32_t bB0 = D + 8192 + bRow * 128;
#pragma unroll
        for (int j = 0; j < 4; j++) {
            uint32_t ac = (((2 * j + aSel) << 4) ^ swx);
            uint32_t bc = (((2 * j + bSel) << 4) ^ swx);
            uint32_t a0[4], a1[4], bb[8];
            ldsm4(a0, aB0 + ac);
            ldsm4(a1, aB0 + 2048 + ac);
            ldsm4(bb + 0, bB0 + bc);
            ldsm4(bb + 4, bB0 + 2048 + bc);
#pragma unroll
            for (int n8 = 0; n8 < 4; n8++) {
                const uint32_t* bp = &bb[(n8 >> 1) * 4 + (n8 & 1) * 2];
                mma16816(acc[0][n8], a0, bp);
                mma16816(acc[1][n8], a1, bp);
            }
            ldsm4(bb + 0, bB0 + 4096 + bc);
            ldsm4(bb + 4, bB0 + 6144 + bc);
#pragma unroll
            for (int n8 = 4; n8 < 8; n8++) {
                const uint32_t* bp = &bb[((n8 - 4) >> 1) * 4 + (n8 & 1) * 2];
                mma16816(acc[0][n8], a0, bp);
                mma16816(acc[1][n8], a1, bp);
            }
        }
        if (lane == 0) MBARRIER_ARRIVE(sb + 32 + st * 8);
        if (tid == 0 && i + 2 < 162) {
            MBARRIER_WAIT_PARITY(sb + 32 + st * 8, ph);
            issue_tile(sb, i + 2, xx, yy, oh, &tw, &tx);
        }
    }

    // epilogue: write fp32 h2 [o][v] + GN2 stats partial; last CTA computes a2/b2
    int g2 = lane >> 2, tc = lane & 3;
    int vb = xy * 256;
    float s = 0.f, q = 0.f;
#pragma unroll
    for (int mt = 0; mt < 2; mt++) {
#pragma unroll
        for (int n8 = 0; n8 < 8; n8++) {
            float* d = acc[mt][n8];
            int o = oh * 64 + wm * 32 + mt * 16 + g2;
            int v = vb + wn * 64 + n8 * 8 + tc * 2;
            *(float2*)&g_h2[o * SP + v] = make_float2(d[0], d[1]);
            *(float2*)&g_h2[(o + 8) * SP + v] = make_float2(d[2], d[3]);
            s += d[0] + d[1] + d[2] + d[3];
            q = fmaf(d[0], d[0], q);
            q = fmaf(d[1], d[1], q);
            q = fmaf(d[2], d[2], q);
            q = fmaf(d[3], d[3], q);
        }
    }
    reduce2_part(s, q, &g_part2[bx * 2]);
    if (last_block(2, 512)) {
        float mu2, inv2;
        finalize_stats(g_part2, 512, 1.0 / (double)(H * SP), mu2, inv2);
        if (tid < 128) {
            float a = gn2w[tid] * inv2;
            g_a2[tid] = a;
            g_b2[tid] = gn2b[tid] - mu2 * a;
        }
    }
}

// ---------------- kernel 5: GN2+GELU in place + chsum partials; last block does SE --
__global__ void __launch_bounds__(256) k_gelu2(const float* __restrict__ sew1,
                                               const float* __restrict__ sew2,
                                               const float* __restrict__ w3) {
    int bx = blockIdx.x;
    int c = bx >> 6;
    int seg = bx & 63;
    int tid = threadIdx.x;
    float a = g_a2[c], b = g_b2[c];
    int base = c * SP + seg * 1024 + tid;
    float s = 0.f;
#pragma unroll
    for (int k = 0; k < 4; k++) {
        int i = base + k * 256;
        float g = geluf(fmaf(a, g_h2[i], b));
        g_h2[i] = g;
        s += g;
    }
    {
        __shared__ float rA[8];
        const unsigned full = 0xffffffffu;
#pragma unroll
        for (int off = 16; off > 0; off >>= 1) s += __shfl_down_sync(full, s, off);
        int lane = tid & 31, wd = tid >> 5;
        if (lane == 0) rA[wd] = s;
        __syncthreads();
        if (tid == 0) {
            float S = 0.f;
            for (int w = 0; w < 8; w++) S += rA[w];
            g_chsump[bx] = S;
        }
    }
    if (last_block(3, 8192)) {
        __shared__ float m[H];
        __shared__ float t1[SED];
        if (tid < 128) {
            float cs = 0.f;
            const float* p = &g_chsump[tid * 64];
            for (int k = 0; k < 64; k++) cs += p[k];
            m[tid] = cs * (1.f / 65536.f);
        }
        __syncthreads();
        if (tid < SED) {
            float acc = 0.f;
            for (int j = 0; j < H; j++) acc = fmaf(sew1[tid * H + j], m[j], acc);
            t1[tid] = geluf(acc);
        }
        __syncthreads();
        if (tid < 128) {
            float acc = 0.f;
#pragma unroll
            for (int j = 0; j < SED; j++) acc = fmaf(sew2[tid * SED + j], t1[j], acc);
            float sg = 1.f / (1.f + expf(-acc));
            for (int o = 0; o < COUT; o++) g_w3eff[o * H + tid] = w3[o * H + tid] * sg;
        }
    }
}

// ---------------- kernel 6: conv3 (1^4, 128->32); last block computes a3/b3 ---------
__global__ void __launch_bounds__(128) k_conv3(const float* __restrict__ gn3w,
                                               const float* __restrict__ gn3b) {
    __shared__ __align__(16) float sw[H * COUT];
    int tid = threadIdx.x;
    for (int i = tid; i < H * COUT; i += 128) {
        int o = i >> 7;
        int c = i & 127;
        sw[c * COUT + o] = g_w3eff[i];
    }
    __syncthreads();
    int v = blockIdx.x * 128 + tid;
    float acc[COUT];
#pragma unroll
    for (int o = 0; o < COUT; o++) acc[o] = 0.f;
    for (int c = 0; c < H; c++) {
        float hv = g_h2[c * SP + v];
        const float4* wr = (const float4*)(&sw[c * COUT]);
#pragma unroll
        for (int o4 = 0; o4 < COUT / 4; o4++) {
            float4 w4 = wr[o4];
            acc[4 * o4 + 0] = fmaf(w4.x, hv, acc[4 * o4 + 0]);
            acc[4 * o4 + 1] = fmaf(w4.y, hv, acc[4 * o4 + 1]);
            acc[4 * o4 + 2] = fmaf(w4.z, hv, acc[4 * o4 + 2]);
            acc[4 * o4 + 3] = fmaf(w4.w, hv, acc[4 * o4 + 3]);
        }
    }
    float s = 0.f, q = 0.f;
#pragma unroll
    for (int o = 0; o < COUT; o++) {
        float v2 = acc[o];
        s += v2;
        q = fmaf(v2, v2, q);
        g_pre[o * SP + v] = v2;
    }
    reduce2_part(s, q, &g_part3[blockIdx.x * 2]);
    if (last_block(4, 512)) {
        float mu3, inv3;
        finalize_stats(g_part3, 512, 1.0 / (double)(COUT * SP), mu3, inv3);
        if (tid < COUT) {
            float a = gn3w[tid] * inv3;
            g_a3[tid] = a;
            g_b3[tid] = gn3b[tid] - mu3 * a;
        }
    }
}

// ---------------- kernel 7: final GN3 -> out ----------------
__global__ void __launch_bounds__(256) k_final(float* __restrict__ out) {
    int base = blockIdx.x * 1024 + threadIdx.x;
#pragma unroll
    for (int k = 0; k < 4; k++) {
        int i = base + k * 256;
        int c = i >> 16;
        out[i] = fmaf(g_a3[c], g_pre[i], g_b3[c]);
    }
}

// ---------------- launcher ----------------
typedef CUresult (CUDAAPI* PFN_tmapEncode)(
    CUtensorMap*, CUtensorMapDataType, cuuint32_t, void*,
    const cuuint64_t*, const cuuint64_t*, const cuuint32_t*, const cuuint32_t*,
    CUtensorMapInterleave, CUtensorMapSwizzle, CUtensorMapL2promotion, CUtensorMapFloatOOBfill);

extern "C" void kernel_launch(void* const* d_in, const int* in_sizes, int n_in,
                              void* d_out, int out_size) {
    const float* x    = (const float*)d_in[0];
    const float* g0w  = (const float*)d_in[1];
    const float* g0b  = (const float*)d_in[2];
    const float* w1   = (const float*)d_in[3];
    const float* gn1w = (const float*)d_in[4];
    const float* gn1b = (const float*)d_in[5];
    const float* w2   = (const float*)d_in[6];
    const float* gn2w = (const float*)d_in[7];
    const float* gn2b = (const float*)d_in[8];
    const float* sew1 = (const float*)d_in[9];
    const float* sew2 = (const float*)d_in[10];
    const float* w3   = (const float*)d_in[11];
    const float* gn3w = (const float*)d_in[12];
    const float* gn3b = (const float*)d_in[13];
    float* out = (float*)d_out;

    PFN_tmapEncode encode = nullptr;
    {
        void* fp = nullptr;
        cudaDriverEntryPointQueryResult qr;
        cudaGetDriverEntryPoint("cuTensorMapEncodeTiled", &fp, cudaEnableDefault, &qr);
        encode = (PFN_tmapEncode)fp;
    }

    void* pw = nullptr; void* px = nullptr;
    cudaGetSymbolAddress(&pw, g_w2h);
    cudaGetSymbolAddress(&px, g_h1h);
    CUtensorMap tw, tx;
    {
        cuuint64_t dims[3] = {128, 128, 81};
        cuuint64_t strides[2] = {256, 32768};
        cuuint32_t box[3] = {64, 64, 1};
        cuuint32_t es[3] = {1, 1, 1};
        encode(&tw, CU_TENSOR_MAP_DATA_TYPE_FLOAT16, 3, pw, dims, strides, box, es,
               CU_TENSOR_MAP_INTERLEAVE_NONE, CU_TENSOR_MAP_SWIZZLE_128B,
               CU_TENSOR_MAP_L2_PROMOTION_L2_128B, CU_TENSOR_MAP_FLOAT_OOB_FILL_NONE);
    }
    {
        cuuint64_t dims[5] = {128, 16, 16, 16, 16};
        cuuint64_t strides[4] = {256, 4096, 65536, 1048576};
        cuuint32_t box[5] = {64, 16, 16, 1, 1};
        cuuint32_t es[5] = {1, 1, 1, 1, 1};
        encode(&tx, CU_TENSOR_MAP_DATA_TYPE_FLOAT16, 5, px, dims, strides, box, es,
               CU_TENSOR_MAP_INTERLEAVE_NONE, CU_TENSOR_MAP_SWIZZLE_128B,
               CU_TENSOR_MAP_L2_PROMOTION_L2_128B, CU_TENSOR_MAP_FLOAT_OOB_FILL_NONE);
    }
    cudaFuncSetAttribute(k_conv2mma, cudaFuncAttributeMaxDynamicSharedMemorySize, SMEM_TOTAL);

    k_stats0wt2<<<1024, 256>>>(x, w2, w1, g0w, g0b);
    k_conv1<<<SP / 128, 128>>>(x, gn1w, gn1b);
    k_gelu1t<<<SP / 128, 256>>>();
    k_conv2mma<<<512, 256, SMEM_TOTAL>>>(tw, tx, gn2w, gn2b);   // launch #4 -> ncu target
    k_gelu2<<<H * 64, 256>>>(sew1, sew2, w3);
    k_conv3<<<SP / 128, 128>>>(gn3w, gn3b);
    k_final<<<(COUT * SP) / 1024, 256>>>(out);
}

// round 12
// speedup vs baseline: 1.0313x; 1.0313x over previous
#include <cuda_runtime.h>
#include <cuda.h>
#include <cuda_fp16.h>
#include <math.h>
#include <stdint.h>

#define SP 65536        /* 16^4 */
#define CIN 32
#define H 128
#define COUT 32
#define SED 8

// ---------------- scratch (device globals) ----------------
__device__ __half g_h1f[H * SP];                     // conv1 out fp16 [c][v]
__device__ __align__(1024) __half g_h1h[SP * H];     // gelu1 out, channel-last fp16 [v][c]
__device__ __align__(1024) __half g_w2h[81 * H * H]; // conv2 weights fp16 [tap][o][c]
__device__ __half g_h2[H * SP];                      // conv2 out fp16 [o][v] -> gelu'd in place
__device__ float g_pre[COUT * SP];
__device__ float g_part0[512 * 2];                   // stats partials: x
__device__ float g_part1[512 * 2];                   // h1
__device__ float g_part2[256 * 2];                   // h2
__device__ float g_part3[512 * 2];                   // pre
__device__ float g_chsump[8192];                     // SE per-block partial sums
__device__ unsigned g_cnt[8];                        // done-counters (self-resetting)
__device__ float g_w1eff[H * CIN];
__device__ float g_bias1[H];
__device__ float g_a1[H], g_b1[H], g_a2[H], g_b2[H], g_a3[COUT], g_b3[COUT];
__device__ float g_w3eff[COUT * H];

// ---------------- PTX helpers (plain sm_90/sm_80 features only) ----------------
__device__ __forceinline__ uint32_t smem_u32(const void* p) {
    uint32_t a;
    asm("{ .reg .u64 t; cvta.to.shared.u64 t, %1; cvt.u32.u64 %0, t; }" : "=r"(a) : "l"(p));
    return a;
}

#define MBARRIER_INIT(mbar, cnt) \
    asm volatile("mbarrier.init.shared.b64 [%0], %1;" :: "r"((uint32_t)(mbar)), "r"((uint32_t)(cnt)) : "memory")

#define MBARRIER_EXPECT_TX(mbar, bytes) \
    asm volatile("mbarrier.arrive.expect_tx.shared.b64 _, [%0], %1;" :: "r"((uint32_t)(mbar)), "r"((uint32_t)(bytes)) : "memory")

#define MBARRIER_ARRIVE(mbar) \
    asm volatile("mbarrier.arrive.shared.b64 _, [%0];" :: "r"((uint32_t)(mbar)) : "memory")

#define MBARRIER_WAIT_PARITY(mbar, ph) do { \
    uint32_t _m = (uint32_t)(mbar); uint32_t _p = (uint32_t)(ph); uint32_t _d; \
    asm volatile("{\n\t.reg .pred p;\n\t" \
        "mbarrier.try_wait.parity.acquire.cta.shared::cta.b64 p, [%1], %2;\n\t" \
        "selp.b32 %0, 1, 0, p;\n\t}" : "=r"(_d) : "r"(_m), "r"(_p) : "memory"); \
    if (!_d) { \
        asm volatile("{\n\t.reg .pred P1;\n\t" \
            "WL_%=:\n\t" \
            "mbarrier.try_wait.parity.acquire.cta.shared::cta.b64 P1, [%0], %1, 0x989680;\n\t" \
            "@P1 bra.uni WD_%=;\n\t" \
            "bra.uni WL_%=;\n\t" \
            "WD_%=:\n\t}" :: "r"(_m), "r"(_p) : "memory"); \
    } \
} while (0)

#define TMA_LOAD_3D(smem, map, c0, c1, c2, mbar) \
    asm volatile("cp.async.bulk.tensor.3d.shared::cta.global.tile.mbarrier::complete_tx::bytes " \
                 "[%0], [%1, {%2, %3, %4}], [%5];" \
                 :: "r"((uint32_t)(smem)), "l"(map), "r"((int)(c0)), "r"((int)(c1)), "r"((int)(c2)), \
                    "r"((uint32_t)(mbar)) : "memory")

#define TMA_LOAD_5D(smem, map, c0, c1, c2, c3, c4, mbar) \
    asm volatile("cp.async.bulk.tensor.5d.shared::cta.global.tile.mbarrier::complete_tx::bytes " \
                 "[%0], [%1, {%2, %3, %4, %5, %6}], [%7];" \
                 :: "r"((uint32_t)(smem)), "l"(map), "r"((int)(c0)), "r"((int)(c1)), "r"((int)(c2)), \
                    "r"((int)(c3)), "r"((int)(c4)), "r"((uint32_t)(mbar)) : "memory")

__device__ __forceinline__ void ldsm4(uint32_t* r, uint32_t addr) {
    asm volatile("ldmatrix.sync.aligned.m8n8.x4.shared.b16 {%0,%1,%2,%3}, [%4];"
                 : "=r"(r[0]), "=r"(r[1]), "=r"(r[2]), "=r"(r[3]) : "r"(addr));
}

__device__ __forceinline__ void mma16816(float* d, const uint32_t* a, const uint32_t* b) {
    asm volatile("mma.sync.aligned.m16n8k16.row.col.f32.f16.f16.f32 "
                 "{%0,%1,%2,%3}, {%4,%5,%6,%7}, {%8,%9}, {%0,%1,%2,%3};"
                 : "+f"(d[0]), "+f"(d[1]), "+f"(d[2]), "+f"(d[3])
                 : "r"(a[0]), "r"(a[1]), "r"(a[2]), "r"(a[3]), "r"(b[0]), "r"(b[1]));
}

__device__ __forceinline__ float geluf(float v) {
    return 0.5f * v * (1.0f + erff(v * 0.70710678118654752f));
}

// block-reduce (s,q); tid0 writes 2 floats to dst (partial record)
__device__ __forceinline__ void reduce2_part(float s, float q, float* dst) {
    __shared__ float rA[32], rB[32];
    const unsigned full = 0xffffffffu;
#pragma unroll
    for (int off = 16; off > 0; off >>= 1) {
        s += __shfl_down_sync(full, s, off);
        q += __shfl_down_sync(full, q, off);
    }
    int lane = threadIdx.x & 31, wid = threadIdx.x >> 5;
    int nw = (blockDim.x + 31) >> 5;
    if (lane == 0) { rA[wid] = s; rB[wid] = q; }
    __syncthreads();
    if (threadIdx.x == 0) {
        float S = 0.f, Q = 0.f;
        for (int w = 0; w < nw; w++) { S += rA[w]; Q += rB[w]; }
        dst[0] = S; dst[1] = Q;
    }
}

// last-block-done: true in the block that completes the counter; self-resets.
__device__ __forceinline__ bool last_block(int idx, unsigned n) {
    __shared__ unsigned lb_done;
    __threadfence();
    if (threadIdx.x == 0) {
        unsigned old = atomicAdd(&g_cnt[idx], 1u);
        lb_done = (old == n - 1) ? 1u : 0u;
        if (lb_done) g_cnt[idx] = 0;
    }
    __syncthreads();
    if (lb_done) __threadfence();
    return lb_done != 0;
}

// reduce n partial pairs cooperatively; broadcast mu, inv to whole block
__device__ __forceinline__ void finalize_stats(const float* part, int n, double invN,
                                               float& mu, float& inv) {
    __shared__ float rA[32], rB[32], bc2[2];
    float s = 0.f, q = 0.f;
    for (int i = threadIdx.x; i < n; i += blockDim.x) {
        s += part[2 * i];
        q += part[2 * i + 1];
    }
    const unsigned full = 0xffffffffu;
#pragma unroll
    for (int off = 16; off > 0; off >>= 1) {
        s += __shfl_down_sync(full, s, off);
        q += __shfl_down_sync(full, q, off);
    }
    int lane = threadIdx.x & 31, wid = threadIdx.x >> 5;
    int nw = (blockDim.x + 31) >> 5;
    if (lane == 0) { rA[wid] = s; rB[wid] = q; }
    __syncthreads();
    if (threadIdx.x == 0) {
        float S = 0.f, Q = 0.f;
        for (int w = 0; w < nw; w++) { S += rA[w]; Q += rB[w]; }
        bc2[0] = S; bc2[1] = Q;
    }
    __syncthreads();
    double m = (double)bc2[0] * invN;
    double var = (double)bc2[1] * invN - m * m;
    mu = (float)m;
    inv = (float)(1.0 / sqrt(var + 1e-5));
}

// ---------------- kernel 1: stats of x (blocks 0..511) + w2 transpose (512..1023) ----
__global__ void __launch_bounds__(256) k_stats0wt2(const float* __restrict__ x,
                                                   const float* __restrict__ w2,
                                                   const float* __restrict__ w1,
                                                   const float* __restrict__ g0w,
                                                   const float* __restrict__ g0b) {
    int bid = blockIdx.x;
    int tid = threadIdx.x;
    if (bid >= 512) {
        __shared__ float swt[2592];
        int base_oc = (bid - 512) * 32;
        const float* wsrc = w2 + base_oc * 81;
        for (int idx = tid; idx < 2592; idx += 256) swt[idx] = wsrc[idx];
        __syncthreads();
        for (int idx = tid; idx < 2592; idx += 256) {
            int t = idx >> 5;
            int ol = idx & 31;
            g_w2h[t * 16384 + base_oc + ol] = __float2half(swt[ol * 81 + t]);
        }
        return;
    }
    float s = 0.f, q = 0.f;
    int base = bid * 4096 + tid;
#pragma unroll
    for (int k = 0; k < 16; k++) {
        float v = x[base + k * 256];
        s += v;
        q = fmaf(v, v, q);
    }
    reduce2_part(s, q, &g_part0[bid * 2]);
    if (last_block(0, 512)) {
        float mu0, inv0;
        finalize_stats(g_part0, 512, 1.0 / (double)(CIN * SP), mu0, inv0);
        if (tid < 128) {
            int o = tid;
            float bias = 0.f;
            for (int c = 0; c < CIN; c++) {
                float a = inv0 * g0w[c];
                float b = g0b[c] - mu0 * a;
                float w = w1[o * CIN + c];
                g_w1eff[o * CIN + c] = w * a;
                bias = fmaf(w, b, bias);
            }
            g_bias1[o] = bias;
        }
    }
}

// ---------------- kernel 2: conv1 (1^4, 32->128); fp16 h1; last block a1/b1 ---------
__global__ void __launch_bounds__(128) k_conv1(const float* __restrict__ x,
                                               const float* __restrict__ gn1w,
                                               const float* __restrict__ gn1b) {
    __shared__ __align__(16) float sw[H * CIN];
    __shared__ float sb[H];
    int tid = threadIdx.x;
    for (int i = tid; i < H * CIN; i += 128) sw[i] = g_w1eff[i];
    sb[tid] = g_bias1[tid];
    __syncthreads();
    int v = blockIdx.x * 128 + tid;
    float xr[CIN];
#pragma unroll
    for (int c = 0; c < CIN; c++) xr[c] = x[c * SP + v];
    float s = 0.f, q = 0.f;
    for (int o = 0; o < H; o++) {
        float acc = sb[o];
        const float4* wr = (const float4*)(&sw[o * CIN]);
#pragma unroll
        for (int c4 = 0; c4 < CIN / 4; c4++) {
            float4 w4 = wr[c4];
            acc = fmaf(w4.x, xr[4 * c4 + 0], acc);
            acc = fmaf(w4.y, xr[4 * c4 + 1], acc);
            acc = fmaf(w4.z, xr[4 * c4 + 2], acc);
            acc = fmaf(w4.w, xr[4 * c4 + 3], acc);
        }
        g_h1f[o * SP + v] = __float2half(acc);
        s += acc;
        q = fmaf(acc, acc, q);
    }
    reduce2_part(s, q, &g_part1[blockIdx.x * 2]);
    if (last_block(1, 512)) {
        float mu1, inv1;
        finalize_stats(g_part1, 512, 1.0 / (double)(H * SP), mu1, inv1);
        float a = gn1w[tid] * inv1;
        g_a1[tid] = a;
        g_b1[tid] = gn1b[tid] - mu1 * a;
    }
}

// ---------------- kernel 3: GN1 + GELU + transpose to channel-last fp16 -------------
__global__ void __launch_bounds__(256) k_gelu1t() {
    __shared__ __align__(16) __half sm[128 * 132];
    int v0 = blockIdx.x * 128;
    int tid = threadIdx.x;
    int cs = tid >> 7;
    int vs = tid & 127;
    for (int c = cs; c < 128; c += 2) {
        float val = __half2float(g_h1f[c * SP + v0 + vs]);
        val = geluf(fmaf(g_a1[c], val, g_b1[c]));
        sm[vs * 132 + c] = __float2half(val);
    }
    __syncthreads();
    uint2* dst = (uint2*)&g_h1h[(size_t)v0 * 128];
    for (int idx = tid; idx < 4096; idx += 256) {
        int row = idx >> 5, part = idx & 31;
        const uint2* src = (const uint2*)&sm[row * 132 + part * 4];
        dst[idx] = *src;
    }
}

// ---------------- kernel 4: conv2 = TMA + ldmatrix + mma.sync, 81 merged tiles ------
// CTA = one (x,y): output 128 o x 256 voxels. 512 thr = 16 warps (4 o x 4 v).
// 2-stage pipeline, stage = A 2x16KB + B 2x32KB = 96KB. Last CTA computes a2/b2.
#define NSTAGE 2
#define STAGE_BYTES 98304
#define SM_DATA 1024
#define SMEM_TOTAL (SM_DATA + NSTAGE * STAGE_BYTES)   /* 197632 */
#define TILE_TX 98304

__device__ __forceinline__ void issue_tile(uint32_t sb, int i, int xx, int yy,
                                           const CUtensorMap* tw, const CUtensorMap* tx) {
    int s = i & 1;
    uint32_t fullb = sb + s * 8;
    MBARRIER_EXPECT_TX(fullb, TILE_TX);
    int dx = i / 27;
    int r27 = i - dx * 27;
    int dy = r27 / 9;
    int r9 = r27 - dy * 9;
    int dz = r9 / 3;
    int dw = r9 - dz * 3;
    uint32_t D = sb + SM_DATA + s * STAGE_BYTES;
    TMA_LOAD_3D(D, tw, 0, 0, i, fullb);
    TMA_LOAD_3D(D + 16384, tw, 64, 0, i, fullb);
    TMA_LOAD_5D(D + 32768, tx, 0, dw - 1, dz - 1, yy + dy - 1, xx + dx - 1, fullb);
    TMA_LOAD_5D(D + 65536, tx, 64, dw - 1, dz - 1, yy + dy - 1, xx + dx - 1, fullb);
}

__global__ void __launch_bounds__(512, 1) k_conv2mma(const __grid_constant__ CUtensorMap tw,
                                                     const __grid_constant__ CUtensorMap tx,
                                                     const float* __restrict__ gn2w,
                                                     const float* __restrict__ gn2b) {
    extern __shared__ __align__(1024) char smem[];
    uint32_t sb = smem_u32(smem);
    int tid = threadIdx.x;
    int lane = tid & 31, wid = tid >> 5;
    int wm = wid & 3, wn = wid >> 2;
    int bx = blockIdx.x;
    int xx = bx >> 4, yy = bx & 15;

    if (tid == 0) {
        for (int s = 0; s < NSTAGE; s++) {
            MBARRIER_INIT(sb + s * 8, 1);                 // full: tx-based
            MBARRIER_INIT(sb + 32 + s * 8, 16);           // empty: 1 arrive/warp (lane 0)
        }
    }
    __syncthreads();
    if (tid == 0) {
        issue_tile(sb, 0, xx, yy, &tw, &tx);
        issue_tile(sb, 1, xx, yy, &tw, &tx);
    }

    float acc[2][8][4];
#pragma unroll
    for (int a = 0; a < 2; a++)
#pragma unroll
        for (int b = 0; b < 8; b++)
#pragma unroll
            for (int cc = 0; cc < 4; cc++) acc[a][b][cc] = 0.f;

    const uint32_t swx = (lane & 7) << 4;
    const uint32_t aSel = lane >> 4;
    const uint32_t bSel = (lane >> 3) & 1;
    const int aRow = wm * 32 + (lane & 15);
    const int bRow = wn * 64 + (lane & 7) + ((lane >> 4) << 3);

    for (int i = 0; i < 81; i++) {
        int st = i & 1;
        int ph = (i >> 1) & 1;
        MBARRIER_WAIT_PARITY(sb + st * 8, ph);
        uint32_t D = sb + SM_DATA + st * STAGE_BYTES;
#pragma unroll
        for (int j = 0; j < 8; j++) {
            int half = j >> 2, jl = j & 3;
            uint32_t aB0 = D + half * 16384 + aRow * 128;
            uint32_t bB0 = D + 32768 + half * 32768 + bRow * 128;
            uint32_t ac = (((2 * jl + aSel) << 4) ^ swx);
            uint32_t bc = (((2 * jl + bSel) << 4) ^ swx);
            uint32_t a0[4], a1[4], bb[8];
            ldsm4(a0, aB0 + ac);
            ldsm4(a1, aB0 + 2048 + ac);
            ldsm4(bb + 0, bB0 + bc);
            ldsm4(bb + 4, bB0 + 2048 + bc);
#pragma unroll
            for (int n8 = 0; n8 < 4; n8++) {
                const uint32_t* bp = &bb[(n8 >> 1) * 4 + (n8 & 1) * 2];
                mma16816(acc[0][n8], a0, bp);
                mma16816(acc[1][n8], a1, bp);
            }
            ldsm4(bb + 0, bB0 + 4096 + bc);
            ldsm4(bb + 4, bB0 + 6144 + bc);
#pragma unroll
            for (int n8 = 4; n8 < 8; n8++) {
                const uint32_t* bp = &bb[((n8 - 4) >> 1) * 4 + (n8 & 1) * 2];
                mma16816(acc[0][n8], a0, bp);
                mma16816(acc[1][n8], a1, bp);
            }
        }
        if (lane == 0) MBARRIER_ARRIVE(sb + 32 + st * 8);
        if (tid == 0 && i + 2 < 81) {
            MBARRIER_WAIT_PARITY(sb + 32 + st * 8, ph);
            issue_tile(sb, i + 2, xx, yy, &tw, &tx);
        }
    }

    // epilogue: write fp16 h2 [o][v] + exact fp32 GN2 stats partial; last CTA a2/b2
    int g2 = lane >> 2, tc = lane & 3;
    int vb = bx * 256;
    float s = 0.f, q = 0.f;
#pragma unroll
    for (int mt = 0; mt < 2; mt++) {
#pragma unroll
        for (int n8 = 0; n8 < 8; n8++) {
            float* d = acc[mt][n8];
            int o = wm * 32 + mt * 16 + g2;
            int v = vb + wn * 64 + n8 * 8 + tc * 2;
            *(__half2*)&g_h2[o * SP + v] = __floats2half2_rn(d[0], d[1]);
            *(__half2*)&g_h2[(o + 8) * SP + v] = __floats2half2_rn(d[2], d[3]);
            s += d[0] + d[1] + d[2] + d[3];
            q = fmaf(d[0], d[0], q);
            q = fmaf(d[1], d[1], q);
            q = fmaf(d[2], d[2], q);
            q = fmaf(d[3], d[3], q);
        }
    }
    reduce2_part(s, q, &g_part2[bx * 2]);
    if (last_block(2, 256)) {
        float mu2, inv2;
        finalize_stats(g_part2, 256, 1.0 / (double)(H * SP), mu2, inv2);
        if (tid < 128) {
            float a = gn2w[tid] * inv2;
            g_a2[tid] = a;
            g_b2[tid] = gn2b[tid] - mu2 * a;
        }
    }
}

// ---------------- kernel 5: GN2+GELU in place (fp16) + chsum; last block does SE ----
__global__ void __launch_bounds__(256) k_gelu2(const float* __restrict__ sew1,
                                               const float* __restrict__ sew2,
                                               const float* __restrict__ w3) {
    int bx = blockIdx.x;
    int c = bx >> 6;
    int seg = bx & 63;
    int tid = threadIdx.x;
    float a = g_a2[c], b = g_b2[c];
    int base = c * SP + seg * 1024 + tid * 2;   // half2 per thread
    float s = 0.f;
#pragma unroll
    for (int k = 0; k < 2; k++) {
        int i = base + k * 512;
        __half2 hv = *(__half2*)&g_h2[i];
        float g0 = geluf(fmaf(a, __half2float(hv.x), b));
        float g1 = geluf(fmaf(a, __half2float(hv.y), b));
        *(__half2*)&g_h2[i] = __floats2half2_rn(g0, g1);
        s += g0 + g1;
    }
    {
        __shared__ float rA[8];
        const unsigned full = 0xffffffffu;
#pragma unroll
        for (int off = 16; off > 0; off >>= 1) s += __shfl_down_sync(full, s, off);
        int lane = tid & 31, wd = tid >> 5;
        if (lane == 0) rA[wd] = s;
        __syncthreads();
        if (tid == 0) {
            float S = 0.f;
            for (int w = 0; w < 8; w++) S += rA[w];
            g_chsump[bx] = S;
        }
    }
    if (last_block(3, 8192)) {
        __shared__ float m[H];
        __shared__ float t1[SED];
        if (tid < 128) {
            float cs = 0.f;
            const float* p = &g_chsump[tid * 64];
            for (int k = 0; k < 64; k++) cs += p[k];
            m[tid] = cs * (1.f / 65536.f);
        }
        __syncthreads();
        if (tid < SED) {
            float acc = 0.f;
            for (int j = 0; j < H; j++) acc = fmaf(sew1[tid * H + j], m[j], acc);
            t1[tid] = geluf(acc);
        }
        __syncthreads();
        if (tid < 128) {
            float acc = 0.f;
#pragma unroll
            for (int j = 0; j < SED; j++) acc = fmaf(sew2[tid * SED + j], t1[j], acc);
            float sg = 1.f / (1.f + expf(-acc));
            for (int o = 0; o < COUT; o++) g_w3eff[o * H + tid] = w3[o * H + tid] * sg;
        }
    }
}

// ---------------- kernel 6: conv3 (1^4, 128->32), fp16 in; last block a3/b3 ---------
__global__ void __launch_bounds__(128) k_conv3(const float* __restrict__ gn3w,
                                               const float* __restrict__ gn3b) {
    __shared__ __align__(16) float sw[H * COUT];
    int tid = threadIdx.x;
    for (int i = tid; i < H * COUT; i += 128) {
        int o = i >> 7;
        int c = i & 127;
        sw[c * COUT + o] = g_w3eff[i];
    }
    __syncthreads();
    int v = blockIdx.x * 128 + tid;
    float acc[COUT];
#pragma unroll
    for (int o = 0; o < COUT; o++) acc[o] = 0.f;
    for (int c = 0; c < H; c++) {
        float hv = __half2float(g_h2[c * SP + v]);
        const float4* wr = (const float4*)(&sw[c * COUT]);
#pragma unroll
        for (int o4 = 0; o4 < COUT / 4; o4++) {
            float4 w4 = wr[o4];
            acc[4 * o4 + 0] = fmaf(w4.x, hv, acc[4 * o4 + 0]);
            acc[4 * o4 + 1] = fmaf(w4.y, hv, acc[4 * o4 + 1]);
            acc[4 * o4 + 2] = fmaf(w4.z, hv, acc[4 * o4 + 2]);
            acc[4 * o4 + 3] = fmaf(w4.w, hv, acc[4 * o4 + 3]);
        }
    }
    float s = 0.f, q = 0.f;
#pragma unroll
    for (int o = 0; o < COUT; o++) {
        float v2 = acc[o];
        s += v2;
        q = fmaf(v2, v2, q);
        g_pre[o * SP + v] = v2;
    }
    reduce2_part(s, q, &g_part3[blockIdx.x * 2]);
    if (last_block(4, 512)) {
        float mu3, inv3;
        finalize_stats(g_part3, 512, 1.0 / (double)(COUT * SP), mu3, inv3);
        if (tid < COUT) {
            float a = gn3w[tid] * inv3;
            g_a3[tid] = a;
            g_b3[tid] = gn3b[tid] - mu3 * a;
        }
    }
}

// ---------------- kernel 7: final GN3 -> out ----------------
__global__ void __launch_bounds__(256) k_final(float* __restrict__ out) {
    int base = blockIdx.x * 1024 + threadIdx.x;
#pragma unroll
    for (int k = 0; k < 4; k++) {
        int i = base + k * 256;
        int c = i >> 16;
        out[i] = fmaf(g_a3[c], g_pre[i], g_b3[c]);
    }
}

// ---------------- launcher ----------------
typedef CUresult (CUDAAPI* PFN_tmapEncode)(
    CUtensorMap*, CUtensorMapDataType, cuuint32_t, void*,
    const cuuint64_t*, const cuuint64_t*, const cuuint32_t*, const cuuint32_t*,
    CUtensorMapInterleave, CUtensorMapSwizzle, CUtensorMapL2promotion, CUtensorMapFloatOOBfill);

extern "C" void kernel_launch(void* const* d_in, const int* in_sizes, int n_in,
                              void* d_out, int out_size) {
    const float* x    = (const float*)d_in[0];
    const float* g0w  = (const float*)d_in[1];
    const float* g0b  = (const float*)d_in[2];
    const float* w1   = (const float*)d_in[3];
    const float* gn1w = (const float*)d_in[4];
    const float* gn1b = (const float*)d_in[5];
    const float* w2   = (const float*)d_in[6];
    const float* gn2w = (const float*)d_in[7];
    const float* gn2b = (const float*)d_in[8];
    const float* sew1 = (const float*)d_in[9];
    const float* sew2 = (const float*)d_in[10];
    const float* w3   = (const float*)d_in[11];
    const float* gn3w = (const float*)d_in[12];
    const float* gn3b = (const float*)d_in[13];
    float* out = (float*)d_out;

    PFN_tmapEncode encode = nullptr;
    {
        void* fp = nullptr;
        cudaDriverEntryPointQueryResult qr;
        cudaGetDriverEntryPoint("cuTensorMapEncodeTiled", &fp, cudaEnableDefault, &qr);
        encode = (PFN_tmapEncode)fp;
    }

    void* pw = nullptr; void* px = nullptr;
    cudaGetSymbolAddress(&pw, g_w2h);
    cudaGetSymbolAddress(&px, g_h1h);
    CUtensorMap tw, tx;
    {
        cuuint64_t dims[3] = {128, 128, 81};
        cuuint64_t strides[2] = {256, 32768};
        cuuint32_t box[3] = {64, 128, 1};
        cuuint32_t es[3] = {1, 1, 1};
        encode(&tw, CU_TENSOR_MAP_DATA_TYPE_FLOAT16, 3, pw, dims, strides, box, es,
               CU_TENSOR_MAP_INTERLEAVE_NONE, CU_TENSOR_MAP_SWIZZLE_128B,
               CU_TENSOR_MAP_L2_PROMOTION_L2_128B, CU_TENSOR_MAP_FLOAT_OOB_FILL_NONE);
    }
    {
        cuuint64_t dims[5] = {128, 16, 16, 16, 16};
        cuuint64_t strides[4] = {256, 4096, 65536, 1048576};
        cuuint32_t box[5] = {64, 16, 16, 1, 1};
        cuuint32_t es[5] = {1, 1, 1, 1, 1};
        encode(&tx, CU_TENSOR_MAP_DATA_TYPE_FLOAT16, 5, px, dims, strides, box, es,
               CU_TENSOR_MAP_INTERLEAVE_NONE, CU_TENSOR_MAP_SWIZZLE_128B,
               CU_TENSOR_MAP_L2_PROMOTION_L2_128B, CU_TENSOR_MAP_FLOAT_OOB_FILL_NONE);
    }
    cudaFuncSetAttribute(k_conv2mma, cudaFuncAttributeMaxDynamicSharedMemorySize, SMEM_TOTAL);

    k_stats0wt2<<<1024, 256>>>(x, w2, w1, g0w, g0b);
    k_conv1<<<SP / 128, 128>>>(x, gn1w, gn1b);
    k_gelu1t<<<SP / 128, 256>>>();
    k_conv2mma<<<256, 512, SMEM_TOTAL>>>(tw, tx, gn2w, gn2b);   // launch #4 -> ncu target
    k_gelu2<<<H * 64, 256>>>(sew1, sew2, w3);
    k_conv3<<<SP / 128, 128>>>(gn3w, gn3b);
    k_final<<<(COUT * SP) / 1024, 256>>>(out);
}

// round 13
// speedup vs baseline: 1.0881x; 1.0551x over previous
#include <cuda_runtime.h>
#include <cuda.h>
#include <cuda_fp16.h>
#include <math.h>
#include <stdint.h>

#define SP 65536        /* 16^4 */
#define CIN 32
#define H 128
#define COUT 32
#define SED 8

// ---------------- scratch (device globals) ----------------
__device__ __half g_h1f[H * SP];                     // conv1 out fp16 [c][v]
__device__ __align__(1024) __half g_h1h[SP * H];     // gelu1 out [v][c] fp16; REUSED as h2^T
__device__ __align__(1024) __half g_w2h[81 * H * H]; // conv2 weights fp16 [tap][o][c]
__device__ __half g_h2[H * SP];                      // conv2 out fp16 [o][v]
__device__ float g_pre[COUT * SP];
__device__ float g_part0[512 * 2];
__device__ float g_part1[512 * 2];
__device__ float g_part2[256 * 2];
__device__ float g_part3[256 * 2];
__device__ float g_chsump[512 * 128];                // SE partials [blk][c]
__device__ unsigned g_cnt[8];
__device__ float g_w1eff[H * CIN];
__device__ float g_bias1[H];
__device__ float g_a1[H], g_b1[H], g_a2[H], g_b2[H], g_a3[COUT], g_b3[COUT];
__device__ __half g_w3h[COUT * H];                   // SE-folded conv3 weights fp16 [o][c]

// ---------------- PTX helpers (plain sm_90/sm_80 features only) ----------------
__device__ __forceinline__ uint32_t smem_u32(const void* p) {
    uint32_t a;
    asm("{ .reg .u64 t; cvta.to.shared.u64 t, %1; cvt.u32.u64 %0, t; }" : "=r"(a) : "l"(p));
    return a;
}

#define MBARRIER_INIT(mbar, cnt) \
    asm volatile("mbarrier.init.shared.b64 [%0], %1;" :: "r"((uint32_t)(mbar)), "r"((uint32_t)(cnt)) : "memory")

#define MBARRIER_EXPECT_TX(mbar, bytes) \
    asm volatile("mbarrier.arrive.expect_tx.shared.b64 _, [%0], %1;" :: "r"((uint32_t)(mbar)), "r"((uint32_t)(bytes)) : "memory")

#define MBARRIER_ARRIVE(mbar) \
    asm volatile("mbarrier.arrive.shared.b64 _, [%0];" :: "r"((uint32_t)(mbar)) : "memory")

#define MBARRIER_WAIT_PARITY(mbar, ph) do { \
    uint32_t _m = (uint32_t)(mbar); uint32_t _p = (uint32_t)(ph); uint32_t _d; \
    asm volatile("{\n\t.reg .pred p;\n\t" \
        "mbarrier.try_wait.parity.acquire.cta.shared::cta.b64 p, [%1], %2;\n\t" \
        "selp.b32 %0, 1, 0, p;\n\t}" : "=r"(_d) : "r"(_m), "r"(_p) : "memory"); \
    if (!_d) { \
        asm volatile("{\n\t.reg .pred P1;\n\t" \
            "WL_%=:\n\t" \
            "mbarrier.try_wait.parity.acquire.cta.shared::cta.b64 P1, [%0], %1, 0x989680;\n\t" \
            "@P1 bra.uni WD_%=;\n\t" \
            "bra.uni WL_%=;\n\t" \
            "WD_%=:\n\t}" :: "r"(_m), "r"(_p) : "memory"); \
    } \
} while (0)

#define TMA_LOAD_3D(smem, map, c0, c1, c2, mbar) \
    asm volatile("cp.async.bulk.tensor.3d.shared::cta.global.tile.mbarrier::complete_tx::bytes " \
                 "[%0], [%1, {%2, %3, %4}], [%5];" \
                 :: "r"((uint32_t)(smem)), "l"(map), "r"((int)(c0)), "r"((int)(c1)), "r"((int)(c2)), \
                    "r"((uint32_t)(mbar)) : "memory")

#define TMA_LOAD_5D(smem, map, c0, c1, c2, c3, c4, mbar) \
    asm volatile("cp.async.bulk.tensor.5d.shared::cta.global.tile.mbarrier::complete_tx::bytes " \
                 "[%0], [%1, {%2, %3, %4, %5, %6}], [%7];" \
                 :: "r"((uint32_t)(smem)), "l"(map), "r"((int)(c0)), "r"((int)(c1)), "r"((int)(c2)), \
                    "r"((int)(c3)), "r"((int)(c4)), "r"((uint32_t)(mbar)) : "memory")

__device__ __forceinline__ void ldsm4(uint32_t* r, uint32_t addr) {
    asm volatile("ldmatrix.sync.aligned.m8n8.x4.shared.b16 {%0,%1,%2,%3}, [%4];"
                 : "=r"(r[0]), "=r"(r[1]), "=r"(r[2]), "=r"(r[3]) : "r"(addr));
}

__device__ __forceinline__ void mma16816(float* d, const uint32_t* a, const uint32_t* b) {
    asm volatile("mma.sync.aligned.m16n8k16.row.col.f32.f16.f16.f32 "
                 "{%0,%1,%2,%3}, {%4,%5,%6,%7}, {%8,%9}, {%0,%1,%2,%3};"
                 : "+f"(d[0]), "+f"(d[1]), "+f"(d[2]), "+f"(d[3])
                 : "r"(a[0]), "r"(a[1]), "r"(a[2]), "r"(a[3]), "r"(b[0]), "r"(b[1]));
}

__device__ __forceinline__ float geluf(float v) {
    return 0.5f * v * (1.0f + erff(v * 0.70710678118654752f));
}

__device__ __forceinline__ void reduce2_part(float s, float q, float* dst) {
    __shared__ float rA[32], rB[32];
    const unsigned full = 0xffffffffu;
#pragma unroll
    for (int off = 16; off > 0; off >>= 1) {
        s += __shfl_down_sync(full, s, off);
        q += __shfl_down_sync(full, q, off);
    }
    int lane = threadIdx.x & 31, wid = threadIdx.x >> 5;
    int nw = (blockDim.x + 31) >> 5;
    if (lane == 0) { rA[wid] = s; rB[wid] = q; }
    __syncthreads();
    if (threadIdx.x == 0) {
        float S = 0.f, Q = 0.f;
        for (int w = 0; w < nw; w++) { S += rA[w]; Q += rB[w]; }
        dst[0] = S; dst[1] = Q;
    }
}

__device__ __forceinline__ bool last_block(int idx, unsigned n) {
    __shared__ unsigned lb_done;
    __threadfence();
    if (threadIdx.x == 0) {
        unsigned old = atomicAdd(&g_cnt[idx], 1u);
        lb_done = (old == n - 1) ? 1u : 0u;
        if (lb_done) g_cnt[idx] = 0;
    }
    __syncthreads();
    if (lb_done) __threadfence();
    return lb_done != 0;
}

__device__ __forceinline__ void finalize_stats(const float* part, int n, double invN,
                                               float& mu, float& inv) {
    __shared__ float rA[32], rB[32], bc2[2];
    float s = 0.f, q = 0.f;
    for (int i = threadIdx.x; i < n; i += blockDim.x) {
        s += part[2 * i];
        q += part[2 * i + 1];
    }
    const unsigned full = 0xffffffffu;
#pragma unroll
    for (int off = 16; off > 0; off >>= 1) {
        s += __shfl_down_sync(full, s, off);
        q += __shfl_down_sync(full, q, off);
    }
    int lane = threadIdx.x & 31, wid = threadIdx.x >> 5;
    int nw = (blockDim.x + 31) >> 5;
    if (lane == 0) { rA[wid] = s; rB[wid] = q; }
    __syncthreads();
    if (threadIdx.x == 0) {
        float S = 0.f, Q = 0.f;
        for (int w = 0; w < nw; w++) { S += rA[w]; Q += rB[w]; }
        bc2[0] = S; bc2[1] = Q;
    }
    __syncthreads();
    double m = (double)bc2[0] * invN;
    double var = (double)bc2[1] * invN - m * m;
    mu = (float)m;
    inv = (float)(1.0 / sqrt(var + 1e-5));
}

// ---------------- kernel 1: stats of x + w2 transpose ----------------
__global__ void __launch_bounds__(256) k_stats0wt2(const float* __restrict__ x,
                                                   const float* __restrict__ w2,
                                                   const float* __restrict__ w1,
                                                   const float* __restrict__ g0w,
                                                   const float* __restrict__ g0b) {
    int bid = blockIdx.x;
    int tid = threadIdx.x;
    if (bid >= 512) {
        __shared__ float swt[2592];
        int base_oc = (bid - 512) * 32;
        const float* wsrc = w2 + base_oc * 81;
        for (int idx = tid; idx < 2592; idx += 256) swt[idx] = wsrc[idx];
        __syncthreads();
        for (int idx = tid; idx < 2592; idx += 256) {
            int t = idx >> 5;
            int ol = idx & 31;
            g_w2h[t * 16384 + base_oc + ol] = __float2half(swt[ol * 81 + t]);
        }
        return;
    }
    float s = 0.f, q = 0.f;
    int base = bid * 4096 + tid;
#pragma unroll
    for (int k = 0; k < 16; k++) {
        float v = x[base + k * 256];
        s += v;
        q = fmaf(v, v, q);
    }
    reduce2_part(s, q, &g_part0[bid * 2]);
    if (last_block(0, 512)) {
        float mu0, inv0;
        finalize_stats(g_part0, 512, 1.0 / (double)(CIN * SP), mu0, inv0);
        if (tid < 128) {
            int o = tid;
            float bias = 0.f;
            for (int c = 0; c < CIN; c++) {
                float a = inv0 * g0w[c];
                float b = g0b[c] - mu0 * a;
                float w = w1[o * CIN + c];
                g_w1eff[o * CIN + c] = w * a;
                bias = fmaf(w, b, bias);
            }
            g_bias1[o] = bias;
        }
    }
}

// ---------------- kernel 2: conv1 (1^4, 32->128), 4-acc ILP; fp16 h1 ----------------
__global__ void __launch_bounds__(128) k_conv1(const float* __restrict__ x,
                                               const float* __restrict__ gn1w,
                                               const float* __restrict__ gn1b) {
    __shared__ __align__(16) float sw[H * CIN];
    __shared__ float sb[H];
    int tid = threadIdx.x;
    for (int i = tid; i < H * CIN; i += 128) sw[i] = g_w1eff[i];
    sb[tid] = g_bias1[tid];
    __syncthreads();
    int v = blockIdx.x * 128 + tid;
    float xr[CIN];
#pragma unroll
    for (int c = 0; c < CIN; c++) xr[c] = x[c * SP + v];
    float s = 0.f, q = 0.f;
    for (int o = 0; o < H; o++) {
        const float4* wr = (const float4*)(&sw[o * CIN]);
        float a0 = 0.f, a1 = 0.f, a2 = 0.f, a3 = 0.f;
#pragma unroll
        for (int g = 0; g < 2; g++) {
            float4 w0 = wr[g * 4 + 0], w1v = wr[g * 4 + 1], w2v = wr[g * 4 + 2], w3v = wr[g * 4 + 3];
            int b = g * 16;
            a0 = fmaf(w0.x, xr[b + 0], a0);  a0 = fmaf(w0.y, xr[b + 1], a0);
            a1 = fmaf(w0.z, xr[b + 2], a1);  a1 = fmaf(w0.w, xr[b + 3], a1);
            a0 = fmaf(w1v.x, xr[b + 4], a0); a0 = fmaf(w1v.y, xr[b + 5], a0);
            a1 = fmaf(w1v.z, xr[b + 6], a1); a1 = fmaf(w1v.w, xr[b + 7], a1);
            a2 = fmaf(w2v.x, xr[b + 8], a2); a2 = fmaf(w2v.y, xr[b + 9], a2);
            a3 = fmaf(w2v.z, xr[b + 10], a3); a3 = fmaf(w2v.w, xr[b + 11], a3);
            a2 = fmaf(w3v.x, xr[b + 12], a2); a2 = fmaf(w3v.y, xr[b + 13], a2);
            a3 = fmaf(w3v.z, xr[b + 14], a3); a3 = fmaf(w3v.w, xr[b + 15], a3);
        }
        float acc = sb[o] + (a0 + a1) + (a2 + a3);
        g_h1f[o * SP + v] = __float2half(acc);
        s += acc;
        q = fmaf(acc, acc, q);
    }
    reduce2_part(s, q, &g_part1[blockIdx.x * 2]);
    if (last_block(1, 512)) {
        float mu1, inv1;
        finalize_stats(g_part1, 512, 1.0 / (double)(H * SP), mu1, inv1);
        float a = gn1w[tid] * inv1;
        g_a1[tid] = a;
        g_b1[tid] = gn1b[tid] - mu1 * a;
    }
}

// ---------------- kernel 3: GN1 + GELU + transpose to channel-last fp16 -------------
__global__ void __launch_bounds__(256) k_gelu1t() {
    __shared__ __align__(16) __half sm[128 * 132];
    int v0 = blockIdx.x * 128;
    int tid = threadIdx.x;
    int cs = tid >> 7;
    int vs = tid & 127;
    for (int c = cs; c < 128; c += 2) {
        float val = __half2float(g_h1f[c * SP + v0 + vs]);
        val = geluf(fmaf(g_a1[c], val, g_b1[c]));
        sm[vs * 132 + c] = __float2half(val);
    }
    __syncthreads();
    uint2* dst = (uint2*)&g_h1h[(size_t)v0 * 128];
    for (int idx = tid; idx < 4096; idx += 256) {
        int row = idx >> 5, part = idx & 31;
        const uint2* src = (const uint2*)&sm[row * 132 + part * 4];
        dst[idx] = *src;
    }
}

// ---------------- kernel 4: conv2 = TMA + ldmatrix + mma.sync (r12 verbatim) --------
#define NSTAGE 2
#define STAGE_BYTES 98304
#define SM_DATA 1024
#define SMEM_TOTAL (SM_DATA + NSTAGE * STAGE_BYTES)
#define TILE_TX 98304

__device__ __forceinline__ void issue_tile(uint32_t sb, int i, int xx, int yy,
                                           const CUtensorMap* tw, const CUtensorMap* tx) {
    int s = i & 1;
    uint32_t fullb = sb + s * 8;
    MBARRIER_EXPECT_TX(fullb, TILE_TX);
    int dx = i / 27;
    int r27 = i - dx * 27;
    int dy = r27 / 9;
    int r9 = r27 - dy * 9;
    int dz = r9 / 3;
    int dw = r9 - dz * 3;
    uint32_t D = sb + SM_DATA + s * STAGE_BYTES;
    TMA_LOAD_3D(D, tw, 0, 0, i, fullb);
    TMA_LOAD_3D(D + 16384, tw, 64, 0, i, fullb);
    TMA_LOAD_5D(D + 32768, tx, 0, dw - 1, dz - 1, yy + dy - 1, xx + dx - 1, fullb);
    TMA_LOAD_5D(D + 65536, tx, 64, dw - 1, dz - 1, yy + dy - 1, xx + dx - 1, fullb);
}

__global__ void __launch_bounds__(512, 1) k_conv2mma(const __grid_constant__ CUtensorMap tw,
                                                     const __grid_constant__ CUtensorMap tx,
                                                     const float* __restrict__ gn2w,
                                                     const float* __restrict__ gn2b) {
    extern __shared__ __align__(1024) char smem[];
    uint32_t sb = smem_u32(smem);
    int tid = threadIdx.x;
    int lane = tid & 31, wid = tid >> 5;
    int wm = wid & 3, wn = wid >> 2;
    int bx = blockIdx.x;
    int xx = bx >> 4, yy = bx & 15;

    if (tid == 0) {
        for (int s = 0; s < NSTAGE; s++) {
            MBARRIER_INIT(sb + s * 8, 1);
            MBARRIER_INIT(sb + 32 + s * 8, 16);
        }
    }
    __syncthreads();
    if (tid == 0) {
        issue_tile(sb, 0, xx, yy, &tw, &tx);
        issue_tile(sb, 1, xx, yy, &tw, &tx);
    }

    float acc[2][8][4];
#pragma unroll
    for (int a = 0; a < 2; a++)
#pragma unroll
        for (int b = 0; b < 8; b++)
#pragma unroll
            for (int cc = 0; cc < 4; cc++) acc[a][b][cc] = 0.f;

    const uint32_t swx = (lane & 7) << 4;
    const uint32_t aSel = lane >> 4;
    const uint32_t bSel = (lane >> 3) & 1;
    const int aRow = wm * 32 + (lane & 15);
    const int bRow = wn * 64 + (lane & 7) + ((lane >> 4) << 3);

    for (int i = 0; i < 81; i++) {
        int st = i & 1;
        int ph = (i >> 1) & 1;
        MBARRIER_WAIT_PARITY(sb + st * 8, ph);
        uint32_t D = sb + SM_DATA + st * STAGE_BYTES;
#pragma unroll
        for (int j = 0; j < 8; j++) {
            int half = j >> 2, jl = j & 3;
            uint32_t aB0 = D + half * 16384 + aRow * 128;
            uint32_t bB0 = D + 32768 + half * 32768 + bRow * 128;
            uint32_t ac = (((2 * jl + aSel) << 4) ^ swx);
            uint32_t bc = (((2 * jl + bSel) << 4) ^ swx);
            uint32_t a0[4], a1[4], bb[8];
            ldsm4(a0, aB0 + ac);
            ldsm4(a1, aB0 + 2048 + ac);
            ldsm4(bb + 0, bB0 + bc);
            ldsm4(bb + 4, bB0 + 2048 + bc);
#pragma unroll
            for (int n8 = 0; n8 < 4; n8++) {
                const uint32_t* bp = &bb[(n8 >> 1) * 4 + (n8 & 1) * 2];
                mma16816(acc[0][n8], a0, bp);
                mma16816(acc[1][n8], a1, bp);
            }
            ldsm4(bb + 0, bB0 + 4096 + bc);
            ldsm4(bb + 4, bB0 + 6144 + bc);
#pragma unroll
            for (int n8 = 4; n8 < 8; n8++) {
                const uint32_t* bp = &bb[((n8 - 4) >> 1) * 4 + (n8 & 1) * 2];
                mma16816(acc[0][n8], a0, bp);
                mma16816(acc[1][n8], a1, bp);
            }
        }
        if (lane == 0) MBARRIER_ARRIVE(sb + 32 + st * 8);
        if (tid == 0 && i + 2 < 81) {
            MBARRIER_WAIT_PARITY(sb + 32 + st * 8, ph);
            issue_tile(sb, i + 2, xx, yy, &tw, &tx);
        }
    }

    int g2 = lane >> 2, tc = lane & 3;
    int vb = bx * 256;
    float s = 0.f, q = 0.f;
#pragma unroll
    for (int mt = 0; mt < 2; mt++) {
#pragma unroll
        for (int n8 = 0; n8 < 8; n8++) {
            float* d = acc[mt][n8];
            int o = wm * 32 + mt * 16 + g2;
            int v = vb + wn * 64 + n8 * 8 + tc * 2;
            *(__half2*)&g_h2[o * SP + v] = __floats2half2_rn(d[0], d[1]);
            *(__half2*)&g_h2[(o + 8) * SP + v] = __floats2half2_rn(d[2], d[3]);
            s += d[0] + d[1] + d[2] + d[3];
            q = fmaf(d[0], d[0], q);
            q = fmaf(d[1], d[1], q);
            q = fmaf(d[2], d[2], q);
            q = fmaf(d[3], d[3], q);
        }
    }
    reduce2_part(s, q, &g_part2[bx * 2]);
    if (last_block(2, 256)) {
        float mu2, inv2;
        finalize_stats(g_part2, 256, 1.0 / (double)(H * SP), mu2, inv2);
        if (tid < 128) {
            float a = gn2w[tid] * inv2;
            g_a2[tid] = a;
            g_b2[tid] = gn2b[tid] - mu2 * a;
        }
    }
}

// ---------------- kernel 5: GN2+GELU + transpose h2 -> g_h1h [v][c]; SE in last -----
__global__ void __launch_bounds__(256) k_gelu2t(const float* __restrict__ sew1,
                                                const float* __restrict__ sew2,
                                                const float* __restrict__ w3) {
    __shared__ __align__(16) __half sm[128 * 132];
    __shared__ float sa[128], sbf[128];
    int v0 = blockIdx.x * 128;
    int tid = threadIdx.x;
    if (tid < 128) { sa[tid] = g_a2[tid]; sbf[tid] = g_b2[tid]; }
    __syncthreads();
    int cs = tid >> 7;
    int vs = tid & 127;
    for (int c = cs; c < 128; c += 2) {
        float val = __half2float(g_h2[c * SP + v0 + vs]);
        val = geluf(fmaf(sa[c], val, sbf[c]));
        sm[vs * 132 + c] = __float2half(val);
    }
    __syncthreads();
    // write h2^T into g_h1h [v][c] (reusing gelu1 buffer; conv2 is done with it)
    uint2* dst = (uint2*)&g_h1h[(size_t)v0 * 128];
    for (int idx = tid; idx < 4096; idx += 256) {
        int row = idx >> 5, part = idx & 31;
        const uint2* src = (const uint2*)&sm[row * 132 + part * 4];
        dst[idx] = *src;
    }
    // per-channel sums over this block's 128 voxels
    if (tid < 128) {
        float s = 0.f;
        for (int vv = 0; vv < 128; vv++) s += __half2float(sm[vv * 132 + tid]);
        g_chsump[blockIdx.x * 128 + tid] = s;
    }
    if (last_block(3, 512)) {
        __shared__ float m[H];
        __shared__ float t1[SED];
        if (tid < 128) {
            float cssum = 0.f;
            for (int k = 0; k < 512; k++) cssum += g_chsump[k * 128 + tid];
            m[tid] = cssum * (1.f / 65536.f);
        }
        __syncthreads();
        if (tid < SED) {
            float acc = 0.f;
            for (int j = 0; j < H; j++) acc = fmaf(sew1[tid * H + j], m[j], acc);
            t1[tid] = geluf(acc);
        }
        __syncthreads();
        if (tid < 128) {
            float acc = 0.f;
#pragma unroll
            for (int j = 0; j < SED; j++) acc = fmaf(sew2[tid * SED + j], t1[j], acc);
            float sg = 1.f / (1.f + expf(-acc));
            for (int o = 0; o < COUT; o++)
                g_w3h[o * H + tid] = __float2half(w3[o * H + tid] * sg);
        }
    }
}

// ---------------- kernel 6: conv3 via tensor cores --------------------------------
// pre[32 o, 65536 v] = w3h[32,128] x h2^T[v,128]. CTA = 256 v (one xy), 256 thr =
// 8 warps (2m x 4n). B via the SAME tx descriptor (two 64c halves), A 8KB swizzled.
#define SM3_A 1024
#define SM3_B 9216
#define SMEM3_TOTAL (SM3_B + 65536)   /* 74752 */

__global__ void __launch_bounds__(256) k_conv3mma(const __grid_constant__ CUtensorMap tx,
                                                  const float* __restrict__ gn3w,
                                                  const float* __restrict__ gn3b) {
    extern __shared__ __align__(1024) char smem[];
    uint32_t sb = smem_u32(smem);
    int tid = threadIdx.x;
    int lane = tid & 31, wid = tid >> 5;
    int wm = wid & 1, wn = wid >> 1;      // 2 m-warps x 4 n-warps
    int bx = blockIdx.x;                   // 0..255 = xy
    int xx = bx >> 4, yy = bx & 15;

    if (tid == 0) MBARRIER_INIT(sb, 1);
    __syncthreads();
    if (tid == 0) {
        MBARRIER_EXPECT_TX(sb, 65536);
        TMA_LOAD_5D(sb + SM3_B, &tx, 0, 0, 0, yy, xx, sb);
        TMA_LOAD_5D(sb + SM3_B + 32768, &tx, 64, 0, 0, yy, xx, sb);
    }
    // A: g_w3h [32 o][128 c] -> smem, two 64c halves, 128B rows, SW128 swizzle
    for (int idx = tid; idx < 4096; idx += 256) {
        int o = idx >> 7;
        int c = idx & 127;
        int h = c >> 6;
        uint32_t off = (uint32_t)(o * 128 + (c & 63) * 2);
        uint32_t swo = off ^ ((off >> 3) & 0x70);
        *(__half*)(smem + SM3_A + h * 4096 + swo) = g_w3h[idx];
    }
    __syncthreads();
    MBARRIER_WAIT_PARITY(sb, 0);

    float acc[8][4];
#pragma unroll
    for (int b = 0; b < 8; b++)
#pragma unroll
        for (int cc = 0; cc < 4; cc++) acc[b][cc] = 0.f;

    const uint32_t swx = (lane & 7) << 4;
    const uint32_t aSel = lane >> 4;
    const uint32_t bSel = (lane >> 3) & 1;
    const int aRow = wm * 16 + (lane & 15);
    const int bRow = wn * 64 + (lane & 7) + ((lane >> 4) << 3);

#pragma unroll
    for (int h = 0; h < 2; h++) {
        uint32_t aB = sb + SM3_A + h * 4096 + aRow * 128;
        uint32_t bB = sb + SM3_B + h * 32768 + bRow * 128;
#pragma unroll
        for (int j = 0; j < 4; j++) {
            uint32_t ac = (((2 * j + aSel) << 4) ^ swx);
            uint32_t bc = (((2 * j + bSel) << 4) ^ swx);
            uint32_t a0[4], bb[8];
            ldsm4(a0, aB + ac);
            ldsm4(bb + 0, bB + bc);
            ldsm4(bb + 4, bB + 2048 + bc);
#pragma unroll
            for (int n8 = 0; n8 < 4; n8++) {
                const uint32_t* bp = &bb[(n8 >> 1) * 4 + (n8 & 1) * 2];
                mma16816(acc[n8], a0, bp);
            }
            ldsm4(bb + 0, bB + 4096 + bc);
            ldsm4(bb + 4, bB + 6144 + bc);
#pragma unroll
            for (int n8 = 4; n8 < 8; n8++) {
                const uint32_t* bp = &bb[((n8 - 4) >> 1) * 4 + (n8 & 1) * 2];
                mma16816(acc[n8], a0, bp);
            }
        }
    }

    // epilogue: pre[o][v] fp32 + GN3 stats partial; last block computes a3/b3
    int g2 = lane >> 2, tc = lane & 3;
    int vb = bx * 256;
    float s = 0.f, q = 0.f;
#pragma unroll
    for (int n8 = 0; n8 < 8; n8++) {
        float* d = acc[n8];
        int o = wm * 16 + g2;
        int v = vb + wn * 64 + n8 * 8 + tc * 2;
        *(float2*)&g_pre[o * SP + v] = make_float2(d[0], d[1]);
        *(float2*)&g_pre[(o + 8) * SP + v] = make_float2(d[2], d[3]);
        s += d[0] + d[1] + d[2] + d[3];
        q = fmaf(d[0], d[0], q);
        q = fmaf(d[1], d[1], q);
        q = fmaf(d[2], d[2], q);
        q = fmaf(d[3], d[3], q);
    }
    reduce2_part(s, q, &g_part3[bx * 2]);
    if (last_block(4, 256)) {
        float mu3, inv3;
        finalize_stats(g_part3, 256, 1.0 / (double)(COUT * SP), mu3, inv3);
        if (tid < COUT) {
            float a = gn3w[tid] * inv3;
            g_a3[tid] = a;
            g_b3[tid] = gn3b[tid] - mu3 * a;
        }
    }
}

// ---------------- kernel 7: final GN3 -> out ----------------
__global__ void __launch_bounds__(256) k_final(float* __restrict__ out) {
    int base = blockIdx.x * 1024 + threadIdx.x;
#pragma unroll
    for (int k = 0; k < 4; k++) {
        int i = base + k * 256;
        int c = i >> 16;
        out[i] = fmaf(g_a3[c], g_pre[i], g_b3[c]);
    }
}

// ---------------- launcher ----------------
typedef CUresult (CUDAAPI* PFN_tmapEncode)(
    CUtensorMap*, CUtensorMapDataType, cuuint32_t, void*,
    const cuuint64_t*, const cuuint64_t*, const cuuint32_t*, const cuuint32_t*,
    CUtensorMapInterleave, CUtensorMapSwizzle, CUtensorMapL2promotion, CUtensorMapFloatOOBfill);

extern "C" void kernel_launch(void* const* d_in, const int* in_sizes, int n_in,
                              void* d_out, int out_size) {
    const float* x    = (const float*)d_in[0];
    const float* g0w  = (const float*)d_in[1];
    const float* g0b  = (const float*)d_in[2];
    const float* w1   = (const float*)d_in[3];
    const float* gn1w = (const float*)d_in[4];
    const float* gn1b = (const float*)d_in[5];
    const float* w2   = (const float*)d_in[6];
    const float* gn2w = (const float*)d_in[7];
    const float* gn2b = (const float*)d_in[8];
    const float* sew1 = (const float*)d_in[9];
    const float* sew2 = (const float*)d_in[10];
    const float* w3   = (const float*)d_in[11];
    const float* gn3w = (const float*)d_in[12];
    const float* gn3b = (const float*)d_in[13];
    float* out = (float*)d_out;

    PFN_tmapEncode encode = nullptr;
    {
        void* fp = nullptr;
        cudaDriverEntryPointQueryResult qr;
        cudaGetDriverEntryPoint("cuTensorMapEncodeTiled", &fp, cudaEnableDefault, &qr);
        encode = (PFN_tmapEncode)fp;
    }

    void* pw = nullptr; void* px = nullptr;
    cudaGetSymbolAddress(&pw, g_w2h);
    cudaGetSymbolAddress(&px, g_h1h);
    CUtensorMap tw, tx;
    {
        cuuint64_t dims[3] = {128, 128, 81};
        cuuint64_t strides[2] = {256, 32768};
        cuuint32_t box[3] = {64, 128, 1};
        cuuint32_t es[3] = {1, 1, 1};
        encode(&tw, CU_TENSOR_MAP_DATA_TYPE_FLOAT16, 3, pw, dims, strides, box, es,
               CU_TENSOR_MAP_INTERLEAVE_NONE, CU_TENSOR_MAP_SWIZZLE_128B,
               CU_TENSOR_MAP_L2_PROMOTION_L2_128B, CU_TENSOR_MAP_FLOAT_OOB_FILL_NONE);
    }
    {
        cuuint64_t dims[5] = {128, 16, 16, 16, 16};
        cuuint64_t strides[4] = {256, 4096, 65536, 1048576};
        cuuint32_t box[5] = {64, 16, 16, 1, 1};
        cuuint32_t es[5] = {1, 1, 1, 1, 1};
        encode(&tx, CU_TENSOR_MAP_DATA_TYPE_FLOAT16, 5, px, dims, strides, box, es,
               CU_TENSOR_MAP_INTERLEAVE_NONE, CU_TENSOR_MAP_SWIZZLE_128B,
               CU_TENSOR_MAP_L2_PROMOTION_L2_128B, CU_TENSOR_MAP_FLOAT_OOB_FILL_NONE);
    }
    cudaFuncSetAttribute(k_conv2mma, cudaFuncAttributeMaxDynamicSharedMemorySize, SMEM_TOTAL);
    cudaFuncSetAttribute(k_conv3mma, cudaFuncAttributeMaxDynamicSharedMemorySize, SMEM3_TOTAL);

    k_stats0wt2<<<1024, 256>>>(x, w2, w1, g0w, g0b);
    k_conv1<<<SP / 128, 128>>>(x, gn1w, gn1b);
    k_gelu1t<<<SP / 128, 256>>>();
    k_conv2mma<<<256, 512, SMEM_TOTAL>>>(tw, tx, gn2w, gn2b);   // launch #4 -> ncu target
    k_gelu2t<<<512, 256>>>(sew1, sew2, w3);
    k_conv3mma<<<256, 256, SMEM3_TOTAL>>>(tx, gn3w, gn3b);
    k_final<<<(COUT * SP) / 1024, 256>>>(out);
}